// round 5
// baseline (speedup 1.0000x reference)
#include <cuda_runtime.h>
#include <cstdint>

#define B_   32
#define CI   64
#define CO   64
#define N_   4096
#define M1   1024      // modes1
#define K_   2049      // output length N/2+1
#define ROWS (B_*CI)   // 2048
#define NCAS 2304      // padded n rows for cas (9 * 256)

// -------- device scratch (static globals; no allocation) --------
__device__ float g_tw[4096];                 // butterfly twiddles: g_tw[h+j] = cas(2*pi*j/(2h))
__device__ float g_casP[NCAS * M1];          // idht cas, [n][k] PERMUTED to mma-frag order, tf32-rounded
__device__ float g_wp[M1 * CI * CO];         // [k][i][o] = w[i,o,k] + w[CI-1-i,o,k]
__device__ float g_wm[M1 * CI * CO];         // [k][i][o] = w[i,o,k] - w[CI-1-i,o,k]
__device__ float g_xhT[M1 * ROWS];           // FHT output, k-major: [k][b*CI+ci]
__device__ float g_ohT[M1 * (B_*CO)];        // mixed modes, k-major: [k][b*CO+o], tf32-rounded

#define TWO_PI_F 6.283185307179586f

__device__ __forceinline__ uint32_t f2tf32(float v) {
    uint32_t o;
    asm("cvt.rna.tf32.f32 %0, %1;" : "=r"(o) : "f"(v));
    return o;
}

// ================= setup kernels =================
__global__ void tw_kernel() {
    int t = blockIdx.x * blockDim.x + threadIdx.x;
    if (t < 1 || t >= 4096) return;
    int h = 1 << (31 - __clz(t));
    int j = t - h;
    float ang = (TWO_PI_F * (float)j) / (float)(2 * h);
    float s, c; sincosf(ang, &s, &c);
    g_tw[t] = c + s;
}

// cas in [n][P] with P the in-chunk fragment permutation:
// P = kc*32 + p,  p = sp*16? no: p bits: slot q = p>>2 (q = sp*4 + t), j = p&3
//   sp = p>>4, t = (p>>2)&3, j = p&3  ->  k = kc*32 + sp*16 + j*4 + t
__global__ void cas_kernel() {
    long idx = (long)blockIdx.x * blockDim.x + threadIdx.x;
    if (idx >= (long)NCAS * M1) return;
    int n = (int)(idx >> 10);
    int P = (int)(idx & 1023);
    int kc = P >> 5, p = P & 31;
    int k = kc * 32 + (p >> 4) * 16 + (p & 3) * 4 + ((p >> 2) & 3);
    float ang = (TWO_PI_F * ((float)k * (float)n)) / 2049.0f;
    float s, c; sincosf(ang, &s, &c);
    ((uint32_t*)g_casP)[idx] = f2tf32(c + s);
}

__global__ void wpm_kernel(const float* __restrict__ w) {
    __shared__ float sp[32][33];
    __shared__ float sm[32][33];
    int i  = blockIdx.z;
    int o0 = blockIdx.y * 32;
    int k0 = blockIdx.x * 32;
    int tx = threadIdx.x, ty = threadIdx.y;
    size_t off1 = ((size_t)i            * CO + (o0 + ty)) * M1 + k0 + tx;
    size_t off2 = ((size_t)(CI - 1 - i) * CO + (o0 + ty)) * M1 + k0 + tx;
    float a = w[off1], b = w[off2];
    sp[ty][tx] = a + b;
    sm[ty][tx] = a - b;
    __syncthreads();
    size_t woff = (size_t)(k0 + ty) * (CI * CO) + (size_t)i * CO + (o0 + tx);
    g_wp[woff] = sp[tx][ty];
    g_wm[woff] = sm[tx][ty];
}

// ================= FHT: 3-phase register-resident radix-16 =================
__global__ void __launch_bounds__(256) fht_kernel(const float* __restrict__ x) {
    __shared__ float s[N_ + N_ / 16];
    const int tid = threadIdx.x;
    const int row = blockIdx.x;
    const float* xr = x + (size_t)row * N_;

#pragma unroll
    for (int it = 0; it < 4; it++) {
        int n = tid * 4 + it * 1024;
        float4 v = *(const float4*)(xr + n);
        int p = n + (n >> 4);
        s[p] = v.x; s[p + 1] = v.y; s[p + 2] = v.z; s[p + 3] = v.w;
    }
    __syncthreads();

    float r[16];
    const int bt = __brev((unsigned)tid) >> 24;
#pragma unroll
    for (int q = 0; q < 16; q++) {
        int br = __brev((unsigned)q) >> 28;
        int idx = br * 256 + bt;
        r[q] = s[idx + (idx >> 4)];
    }
#pragma unroll
    for (int hs = 1; hs <= 8; hs <<= 1) {
#pragma unroll
        for (int q = 0; q < 16; q++) {
            if ((q & hs) == 0) {
                float tw = g_tw[hs + (q & (hs - 1))];
                float u = r[q], v = r[q + hs];
                float tv = tw * v;
                r[q] = u + tv; r[q + hs] = u - tv;
            }
        }
    }
    __syncthreads();
#pragma unroll
    for (int q = 0; q < 16; q++) {
        int idx = 16 * tid + q;
        s[idx + (idx >> 4)] = r[q];
    }
    __syncthreads();

    const int hi = tid >> 4, lo = tid & 15;
#pragma unroll
    for (int q = 0; q < 16; q++) {
        int idx = hi * 256 + q * 16 + lo;
        r[q] = s[idx + (idx >> 4)];
    }
#pragma unroll
    for (int hb = 1; hb <= 8; hb <<= 1) {
        int h = hb * 16;
#pragma unroll
        for (int q = 0; q < 16; q++) {
            if ((q & hb) == 0) {
                float tw = g_tw[h + (q & (hb - 1)) * 16 + lo];
                float u = r[q], v = r[q + hb];
                float tv = tw * v;
                r[q] = u + tv; r[q + hb] = u - tv;
            }
        }
    }
    __syncthreads();
#pragma unroll
    for (int q = 0; q < 16; q++) {
        int idx = hi * 256 + q * 16 + lo;
        s[idx + (idx >> 4)] = r[q];
    }
    __syncthreads();

#pragma unroll
    for (int q = 0; q < 16; q++) {
        int idx = q * 256 + tid;
        r[q] = s[idx + (idx >> 4)];
    }
#pragma unroll
    for (int hb = 1; hb <= 8; hb <<= 1) {
        int h = hb * 256;
#pragma unroll
        for (int q = 0; q < 16; q++) {
            if ((q & hb) == 0) {
                float tw = g_tw[h + (q & (hb - 1)) * 256 + tid];
                float u = r[q], v = r[q + hb];
                float tv = tw * v;
                r[q] = u + tv; r[q + hb] = u - tv;
            }
        }
    }
#pragma unroll
    for (int q = 0; q < 4; q++)
        g_xhT[(size_t)(q * 256 + tid) * ROWS + row] = r[q];
}

// ================= mode mixing =================
__global__ void __launch_bounds__(256) mix_kernel() {
    int k = blockIdx.x;
    __shared__ float sX [ROWS];
    __shared__ float sWp[CI * CO];
    __shared__ float sWm[CI * CO];
    const float* Xk = g_xhT + (size_t)k * ROWS;
    const float* wp = g_wp  + (size_t)k * CI * CO;
    const float* wm = g_wm  + (size_t)k * CI * CO;
    for (int i = threadIdx.x; i < ROWS; i += 256) sX[i] = Xk[i];
    for (int i = threadIdx.x; i < CI * CO; i += 256) { sWp[i] = wp[i]; sWm[i] = wm[i]; }
    __syncthreads();
    int o  = threadIdx.x & 63;
    int bq = threadIdx.x >> 6;
    float acc[8];
#pragma unroll
    for (int rr = 0; rr < 8; rr++) acc[rr] = 0.f;
    for (int i = 0; i < CI; i++) {
        float wpv = sWp[i * CO + o];
        float wmv = sWm[i * CO + o];
#pragma unroll
        for (int rr = 0; rr < 8; rr++) {
            int b = bq * 8 + rr;
            acc[rr] += sX[b * CI + i] * wpv;
            acc[rr] += sX[(B_ - 1 - b) * CI + i] * wmv;
        }
    }
    uint32_t* ok = (uint32_t*)(g_ohT + (size_t)k * (B_ * CO));
#pragma unroll
    for (int rr = 0; rr < 8; rr++)
        ok[(bq * 8 + rr) * CO + o] = f2tf32(0.5f * acc[rr]);
}

// ================= idht GEMM: mma.sync tf32 (sm_80+ portable) =================
// out[m][n] = (1/2049) * sum_k A[m][k] * B[n][k]
//   A[m][k] = g_ohT[k][m]  (k-major, transpose-staged to smem)
//   B[n][k] = g_casP[n][P] (pre-permuted fragment order)
#define GBM 128
#define GBN 256
#define GBK 32
#define GNCH (M1 / GBK)                   // 32
#define GEMM_SMEM (2*GBM*GBK*4 + 2*GBN*GBK*4)   // 32KB + 64KB = 96KB

__device__ __forceinline__ int swz(int r) { return ((r & 1) << 2) | ((r >> 1) & 3); }

#define MMA8(d, a0, a1, a2, a3, b0, b1) \
    asm volatile("mma.sync.aligned.m16n8k8.row.col.f32.tf32.tf32.f32 " \
        "{%0,%1,%2,%3}, {%4,%5,%6,%7}, {%8,%9}, {%0,%1,%2,%3};" \
        : "+f"((d)[0]), "+f"((d)[1]), "+f"((d)[2]), "+f"((d)[3]) \
        : "r"(a0), "r"(a1), "r"(a2), "r"(a3), "r"(b0), "r"(b1))

__global__ void __launch_bounds__(256, 1) gemm_kernel(float* __restrict__ out) {
    extern __shared__ float smem[];
    float* sA[2] = { smem,               smem + GBM * GBK };
    float* sB[2] = { smem + 2*GBM*GBK,   smem + 2*GBM*GBK + GBN * GBK };

    const int tid  = threadIdx.x;
    const int wid  = tid >> 5;
    const int lane = tid & 31;
    const int g    = lane >> 2;        // fragment group (row)
    const int t    = lane & 3;         // fragment thread-in-group (k)
    const int wm   = wid & 1;          // warp M index (0..1)
    const int wn   = wid >> 1;         // warp N index (0..3)
    const int m0   = blockIdx.y * GBM;
    const int n0   = blockIdx.x * GBN;

    // ---- staging maps ----
    // A: thread -> (m = tid&127, sp = tid>>7); 16 scalar LDG (coalesced over m), 4 STS.128
    const int smA = tid & 127;
    const int spA = tid >> 7;
    // B: thread -> (q = tid&7, nr = tid>>3); 8x (LDG.128 + STS.128)
    const int qB  = tid & 7;
    const int nrB = tid >> 3;

    const float* Ag = g_ohT + m0;                        // [k][m]
    const float* Bg = g_casP + (size_t)n0 * M1;          // [n][P]

    float acc[4][8][4];
#pragma unroll
    for (int a = 0; a < 4; a++)
#pragma unroll
        for (int b = 0; b < 8; b++)
#pragma unroll
            for (int c = 0; c < 4; c++) acc[a][b][c] = 0.f;

    float  ra[16];
    float4 rb[8];

    // prefetch chunk 0
#pragma unroll
    for (int tt = 0; tt < 4; tt++)
#pragma unroll
        for (int j = 0; j < 4; j++)
            ra[tt * 4 + j] = Ag[(size_t)(spA * 16 + 4 * j + tt) * ROWS + smA];
#pragma unroll
    for (int it = 0; it < 8; it++)
        rb[it] = *(const float4*)(Bg + (size_t)(nrB + 32 * it) * M1 + qB * 4);

    for (int c = 0; c < GNCH; c++) {
        const int bsel = c & 1;
        float* Ab = sA[bsel];
        float* Bb = sB[bsel];
        // ---- STS staged regs (conflict-free swizzled) ----
#pragma unroll
        for (int tt = 0; tt < 4; tt++) {
            float4 v = make_float4(__uint_as_float(f2tf32(ra[tt*4+0])),
                                   __uint_as_float(f2tf32(ra[tt*4+1])),
                                   __uint_as_float(f2tf32(ra[tt*4+2])),
                                   __uint_as_float(f2tf32(ra[tt*4+3])));
            int slot = (spA * 4 + tt) ^ swz(smA);
            *(float4*)(Ab + smA * 32 + slot * 4) = v;
        }
#pragma unroll
        for (int it = 0; it < 8; it++) {
            int n = nrB + 32 * it;
            int slot = qB ^ swz(n);
            *(float4*)(Bb + n * 32 + slot * 4) = rb[it];
        }
        // ---- prefetch chunk c+1 ----
        if (c + 1 < GNCH) {
            const int kb = (c + 1) * GBK;
#pragma unroll
            for (int tt = 0; tt < 4; tt++)
#pragma unroll
                for (int j = 0; j < 4; j++)
                    ra[tt * 4 + j] = Ag[(size_t)(kb + spA * 16 + 4 * j + tt) * ROWS + smA];
#pragma unroll
            for (int it = 0; it < 8; it++)
                rb[it] = *(const float4*)(Bg + (size_t)(nrB + 32 * it) * M1 + kb + qB * 4);
        }
        __syncthreads();
        // ---- MMA over buffer bsel ----
#pragma unroll
        for (int sp = 0; sp < 2; sp++) {
            uint4 bf[8];
#pragma unroll
            for (int nt = 0; nt < 8; nt++) {
                int row = wn * 64 + nt * 8 + g;
                int slot = (sp * 4 + t) ^ swz(row);
                bf[nt] = *(const uint4*)(Bb + row * 32 + slot * 4);
            }
#pragma unroll
            for (int mt = 0; mt < 4; mt++) {
                int rowa = wm * 64 + mt * 16 + g;
                int slot = (sp * 4 + t) ^ swz(rowa);          // swz(rowa+8) == swz(rowa)
                uint4 alo = *(const uint4*)(Ab + rowa * 32 + slot * 4);
                uint4 ahi = *(const uint4*)(Ab + (rowa + 8) * 32 + slot * 4);
#pragma unroll
                for (int nt = 0; nt < 8; nt++) {
                    MMA8(acc[mt][nt], alo.x, ahi.x, alo.y, ahi.y, bf[nt].x, bf[nt].y);
                    MMA8(acc[mt][nt], alo.z, ahi.z, alo.w, ahi.w, bf[nt].z, bf[nt].w);
                }
            }
        }
        // next iter's STS targets the other buffer; its hazard partner (MMA c-1)
        // is fenced by this loop's single __syncthreads.
    }

    // ---- epilogue ----
    const float inv = 1.0f / 2049.0f;
#pragma unroll
    for (int mt = 0; mt < 4; mt++) {
        int row = m0 + wm * 64 + mt * 16 + g;
#pragma unroll
        for (int nt = 0; nt < 8; nt++) {
            int col = n0 + wn * 64 + nt * 8 + t * 2;
            if (col < K_) {
                float* p0 = out + (size_t)row * K_ + col;
                float* p1 = out + (size_t)(row + 8) * K_ + col;
                p0[0] = acc[mt][nt][0] * inv;
                p1[0] = acc[mt][nt][2] * inv;
                if (col + 1 < K_) {
                    p0[1] = acc[mt][nt][1] * inv;
                    p1[1] = acc[mt][nt][3] * inv;
                }
            }
        }
    }
}

// ================= launch =================
extern "C" void kernel_launch(void* const* d_in, const int* in_sizes, int n_in,
                              void* d_out, int out_size) {
    const float* x = (const float*)d_in[0];
    const float* w = (const float*)d_in[1];
    float* out = (float*)d_out;

    cudaFuncSetAttribute(gemm_kernel, cudaFuncAttributeMaxDynamicSharedMemorySize, GEMM_SMEM);

    tw_kernel<<<16, 256>>>();
    cas_kernel<<<(NCAS * M1 + 255) / 256, 256>>>();
    wpm_kernel<<<dim3(32, 2, 64), dim3(32, 32)>>>(w);
    fht_kernel<<<ROWS, 256>>>(x);
    mix_kernel<<<M1, 256>>>();
    gemm_kernel<<<dim3(NCAS / GBN, ROWS / GBM), 256, GEMM_SMEM>>>(out);
}

// round 7
// speedup vs baseline: 1.0357x; 1.0357x over previous
#include <cuda_runtime.h>
#include <cstdint>

#define B_   32
#define CI   64
#define CO   64
#define N_   4096
#define M1   1024      // modes1
#define K_   2049      // output length N/2+1
#define ROWS (B_*CI)   // 2048
#define NCAS 2304      // padded n rows for cas (9 * 256)

// -------- device scratch (static globals; no allocation) --------
__device__ float g_tw[4096];                 // butterfly twiddles: g_tw[h+j] = cas(2*pi*j/(2h))
__device__ float g_casP[NCAS * M1];          // idht cas, [n][k] PERMUTED to mma-frag order, tf32-rounded
__device__ float g_wp[M1 * 32 * CO];         // [k][i<32][o] = w[i,o,k] + w[63-i,o,k]   (symmetric half)
__device__ float g_wm[M1 * 32 * CO];         // [k][i<32][o] = w[i,o,k] - w[63-i,o,k]   (antisym half)
__device__ float g_xhT[M1 * ROWS];           // FHT output, k-major: [k][b*CI+ci]
__device__ float g_ohT[M1 * (B_*CO)];        // mixed modes, k-major: [k][b*CO+o], tf32-rounded

#define TWO_PI_F 6.283185307179586f

__device__ __forceinline__ uint32_t f2tf32(float v) {
    uint32_t o;
    asm("cvt.rna.tf32.f32 %0, %1;" : "=r"(o) : "f"(v));
    return o;
}

// ================= setup kernels =================
__global__ void tw_kernel() {
    int t = blockIdx.x * blockDim.x + threadIdx.x;
    if (t < 1 || t >= 4096) return;
    int h = 1 << (31 - __clz(t));
    int j = t - h;
    float ang = (TWO_PI_F * (float)j) / (float)(2 * h);
    float s, c; sincosf(ang, &s, &c);
    g_tw[t] = c + s;
}

// cas in [n][P] with P the in-chunk fragment permutation:
//   P = kc*32 + p; k = kc*32 + (p>>4)*16 + (p&3)*4 + ((p>>2)&3)
// Angle computed with the reference's f32 op order, then exactly range-reduced
// mod 2pi (13-bit + 24-bit split; q*TPH exact for q<=1150) so sincosf takes
// its fast path instead of Payne-Hanek.
__global__ void cas_kernel() {
    long idx = (long)blockIdx.x * blockDim.x + threadIdx.x;
    if (idx >= (long)NCAS * M1) return;
    int n = (int)(idx >> 10);
    int P = (int)(idx & 1023);
    int kc = P >> 5, p = P & 31;
    int k = kc * 32 + (p >> 4) * 16 + (p & 3) * 4 + ((p >> 2) & 3);
    float ang = (TWO_PI_F * ((float)k * (float)n)) / 2049.0f;   // <= ~7224
    float q = rintf(ang * 0.15915494309189535f);                // <= 1150
    float r = fmaf(-q, 6.2822265625f, ang);                     // exact (13b*11b)
    r = fmaf(-q, 9.5874467958647648e-4f, r);                    // |r| <= pi + eps
    float s, c2; sincosf(r, &s, &c2);
    ((uint32_t*)g_casP)[idx] = f2tf32(c2 + s);
}

// fold + transpose weights, halved via i<->63-i symmetry
__global__ void wpm_kernel(const float* __restrict__ w) {
    __shared__ float sp[32][33];
    __shared__ float sm[32][33];
    int i  = blockIdx.z;                // 0..31
    int o0 = blockIdx.y * 32;
    int k0 = blockIdx.x * 32;
    int tx = threadIdx.x, ty = threadIdx.y;
    size_t off1 = ((size_t)i        * CO + (o0 + ty)) * M1 + k0 + tx;
    size_t off2 = ((size_t)(63 - i) * CO + (o0 + ty)) * M1 + k0 + tx;
    float a = w[off1], b = w[off2];
    sp[ty][tx] = a + b;
    sm[ty][tx] = a - b;
    __syncthreads();
    size_t woff = (size_t)(k0 + ty) * (32 * CO) + (size_t)i * CO + (o0 + tx);
    g_wp[woff] = sp[tx][ty];
    g_wm[woff] = sm[tx][ty];
}

// ================= FHT: 3-phase register-resident radix-16 =================
__global__ void __launch_bounds__(256) fht_kernel(const float* __restrict__ x) {
    __shared__ float s[N_ + N_ / 16];
    const int tid = threadIdx.x;
    const int row = blockIdx.x;
    const float* xr = x + (size_t)row * N_;

#pragma unroll
    for (int it = 0; it < 4; it++) {
        int n = tid * 4 + it * 1024;
        float4 v = *(const float4*)(xr + n);
        int p = n + (n >> 4);
        s[p] = v.x; s[p + 1] = v.y; s[p + 2] = v.z; s[p + 3] = v.w;
    }
    __syncthreads();

    float r[16];
    const int bt = __brev((unsigned)tid) >> 24;
#pragma unroll
    for (int q = 0; q < 16; q++) {
        int br = __brev((unsigned)q) >> 28;
        int idx = br * 256 + bt;
        r[q] = s[idx + (idx >> 4)];
    }
#pragma unroll
    for (int hs = 1; hs <= 8; hs <<= 1) {
#pragma unroll
        for (int q = 0; q < 16; q++) {
            if ((q & hs) == 0) {
                float tw = g_tw[hs + (q & (hs - 1))];
                float u = r[q], v = r[q + hs];
                float tv = tw * v;
                r[q] = u + tv; r[q + hs] = u - tv;
            }
        }
    }
    __syncthreads();
#pragma unroll
    for (int q = 0; q < 16; q++) {
        int idx = 16 * tid + q;
        s[idx + (idx >> 4)] = r[q];
    }
    __syncthreads();

    const int hi = tid >> 4, lo = tid & 15;
#pragma unroll
    for (int q = 0; q < 16; q++) {
        int idx = hi * 256 + q * 16 + lo;
        r[q] = s[idx + (idx >> 4)];
    }
#pragma unroll
    for (int hb = 1; hb <= 8; hb <<= 1) {
        int h = hb * 16;
#pragma unroll
        for (int q = 0; q < 16; q++) {
            if ((q & hb) == 0) {
                float tw = g_tw[h + (q & (hb - 1)) * 16 + lo];
                float u = r[q], v = r[q + hb];
                float tv = tw * v;
                r[q] = u + tv; r[q + hb] = u - tv;
            }
        }
    }
    __syncthreads();
#pragma unroll
    for (int q = 0; q < 16; q++) {
        int idx = hi * 256 + q * 16 + lo;
        s[idx + (idx >> 4)] = r[q];
    }
    __syncthreads();

#pragma unroll
    for (int q = 0; q < 16; q++) {
        int idx = q * 256 + tid;
        r[q] = s[idx + (idx >> 4)];
    }
#pragma unroll
    for (int hb = 1; hb <= 8; hb <<= 1) {
        int h = hb * 256;
#pragma unroll
        for (int q = 0; q < 16; q++) {
            if ((q & hb) == 0) {
                float tw = g_tw[h + (q & (hb - 1)) * 256 + tid];
                float u = r[q], v = r[q + hb];
                float tv = tw * v;
                r[q] = u + tv; r[q + hb] = u - tv;
            }
        }
    }
#pragma unroll
    for (int q = 0; q < 4; q++)
        g_xhT[(size_t)(q * 256 + tid) * ROWS + row] = r[q];
}

// ================= mode mixing (symmetry-folded, K=32) =================
__global__ void __launch_bounds__(256) mix_kernel() {
    int k = blockIdx.x;
    __shared__ float sYp[B_ * 32];      // [b][i<32] = X[b][i] + X[b][63-i]
    __shared__ float sYm[B_ * 32];      // [b][i<32] = X[b][i] - X[b][63-i]
    __shared__ float sWp[32 * CO];
    __shared__ float sWm[32 * CO];
    const float* Xk = g_xhT + (size_t)k * ROWS;
    const float* wp = g_wp  + (size_t)k * 32 * CO;
    const float* wm = g_wm  + (size_t)k * 32 * CO;
    for (int idx = threadIdx.x; idx < B_ * 32; idx += 256) {
        int b = idx >> 5, i = idx & 31;
        float u = Xk[b * 64 + i], v = Xk[b * 64 + 63 - i];
        sYp[idx] = u + v;
        sYm[idx] = u - v;
    }
    for (int idx = threadIdx.x; idx < 32 * CO; idx += 256) { sWp[idx] = wp[idx]; sWm[idx] = wm[idx]; }
    __syncthreads();
    int o  = threadIdx.x & 63;
    int bq = threadIdx.x >> 6;
    float acc[8];
#pragma unroll
    for (int rr = 0; rr < 8; rr++) acc[rr] = 0.f;
    for (int i = 0; i < 32; i++) {
        float wpv = sWp[i * CO + o];
        float wmv = sWm[i * CO + o];
#pragma unroll
        for (int rr = 0; rr < 8; rr++) {
            int b = bq * 8 + rr;
            acc[rr] += sYp[b * 32 + i] * wpv;
            acc[rr] += sYm[(31 - b) * 32 + i] * wmv;
        }
    }
    uint32_t* ok = (uint32_t*)(g_ohT + (size_t)k * (B_ * CO));
#pragma unroll
    for (int rr = 0; rr < 8; rr++)
        ok[(bq * 8 + rr) * CO + o] = f2tf32(0.5f * acc[rr]);
}

// ================= idht GEMM: mma.sync tf32, 512 threads =================
// out[m][n] = (1/2049) * sum_k A[m][k] * B[n][k]
//   A[m][k] = g_ohT[k][m]  (k-major, transpose-staged, already tf32)
//   B[n][k] = g_casP[n][P] (pre-permuted fragment order, already tf32)
#define GBM 128
#define GBN 256
#define GBK 32
#define GNCH (M1 / GBK)                         // 32
#define GEMM_SMEM (2*GBM*GBK*4 + 2*GBN*GBK*4)   // 96KB

__device__ __forceinline__ int swz(int r) { return ((r & 1) << 2) | ((r >> 1) & 3); }

#define MMA8(d, a0, a1, a2, a3, b0, b1) \
    asm volatile("mma.sync.aligned.m16n8k8.row.col.f32.tf32.tf32.f32 " \
        "{%0,%1,%2,%3}, {%4,%5,%6,%7}, {%8,%9}, {%0,%1,%2,%3};" \
        : "+f"((d)[0]), "+f"((d)[1]), "+f"((d)[2]), "+f"((d)[3]) \
        : "r"(a0), "r"(a1), "r"(a2), "r"(a3), "r"(b0), "r"(b1))

__global__ void __launch_bounds__(512, 1) gemm_kernel(float* __restrict__ out) {
    extern __shared__ float smem[];
    float* sA[2] = { smem,               smem + GBM * GBK };
    float* sB[2] = { smem + 2*GBM*GBK,   smem + 2*GBM*GBK + GBN * GBK };

    const int tid  = threadIdx.x;
    const int wid  = tid >> 5;
    const int lane = tid & 31;
    const int g    = lane >> 2;        // fragment group (row)
    const int t    = lane & 3;         // fragment thread-in-group (k)
    const int wm   = wid & 3;          // warp M index (0..3), 32-row strip
    const int wn   = wid >> 2;         // warp N index (0..3), 64-col strip
    const int m0   = blockIdx.y * GBM;
    const int n0   = blockIdx.x * GBN;

    // staging maps
    const int smA = tid & 127;         // m row
    const int spA = tid >> 7;          // 0..3 -> slots spA*2, spA*2+1
    const int qB  = tid & 7;           // k-slot
    const int nrB = tid >> 3;          // 0..63 -> rows nrB + 64*it

    const float* Ag = g_ohT + m0;                        // [k][m]
    const float* Bg = g_casP + (size_t)n0 * M1;          // [n][P]

    float acc[2][8][4];
#pragma unroll
    for (int a = 0; a < 2; a++)
#pragma unroll
        for (int b = 0; b < 8; b++)
#pragma unroll
            for (int c = 0; c < 4; c++) acc[a][b][c] = 0.f;

    float  ra[8];
    float4 rb[4];

    // prefetch chunk 0 (slot q holds k = (q>>2)*16 + 4j + (q&3) at vector lane j)
#pragma unroll
    for (int qi = 0; qi < 2; qi++) {
        int q = spA * 2 + qi;
#pragma unroll
        for (int j = 0; j < 4; j++)
            ra[qi * 4 + j] = Ag[(size_t)((q >> 2) * 16 + 4 * j + (q & 3)) * ROWS + smA];
    }
#pragma unroll
    for (int it = 0; it < 4; it++)
        rb[it] = *(const float4*)(Bg + (size_t)(nrB + 64 * it) * M1 + qB * 4);

    for (int c = 0; c < GNCH; c++) {
        const int bsel = c & 1;
        float* Ab = sA[bsel];
        float* Bb = sB[bsel];
        // ---- STS staged regs (swizzled) ----
#pragma unroll
        for (int qi = 0; qi < 2; qi++) {
            int q = spA * 2 + qi;
            float4 v = make_float4(ra[qi*4+0], ra[qi*4+1], ra[qi*4+2], ra[qi*4+3]);
            *(float4*)(Ab + smA * 32 + (q ^ swz(smA)) * 4) = v;
        }
#pragma unroll
        for (int it = 0; it < 4; it++) {
            int n = nrB + 64 * it;
            *(float4*)(Bb + n * 32 + (qB ^ swz(n)) * 4) = rb[it];
        }
        // ---- prefetch chunk c+1 ----
        if (c + 1 < GNCH) {
            const int kb = (c + 1) * GBK;
#pragma unroll
            for (int qi = 0; qi < 2; qi++) {
                int q = spA * 2 + qi;
#pragma unroll
                for (int j = 0; j < 4; j++)
                    ra[qi * 4 + j] = Ag[(size_t)(kb + (q >> 2) * 16 + 4 * j + (q & 3)) * ROWS + smA];
            }
#pragma unroll
            for (int it = 0; it < 4; it++)
                rb[it] = *(const float4*)(Bg + (size_t)(nrB + 64 * it) * M1 + kb + qB * 4);
        }
        __syncthreads();
        // ---- MMA over buffer bsel ----
#pragma unroll
        for (int sp = 0; sp < 2; sp++) {
            uint4 af[2][2];
#pragma unroll
            for (int mt = 0; mt < 2; mt++) {
                int rowa = wm * 32 + mt * 16 + g;
                int slot = (sp * 4 + t) ^ swz(rowa);          // swz(rowa+8) == swz(rowa)
                af[mt][0] = *(const uint4*)(Ab + rowa * 32 + slot * 4);
                af[mt][1] = *(const uint4*)(Ab + (rowa + 8) * 32 + slot * 4);
            }
#pragma unroll
            for (int nt = 0; nt < 8; nt++) {
                int row = wn * 64 + nt * 8 + g;
                int slot = (sp * 4 + t) ^ swz(row);
                uint4 bf = *(const uint4*)(Bb + row * 32 + slot * 4);
#pragma unroll
                for (int mt = 0; mt < 2; mt++) {
                    MMA8(acc[mt][nt], af[mt][0].x, af[mt][1].x, af[mt][0].y, af[mt][1].y, bf.x, bf.y);
                    MMA8(acc[mt][nt], af[mt][0].z, af[mt][1].z, af[mt][0].w, af[mt][1].w, bf.z, bf.w);
                }
            }
        }
        // STS(c+1) into the other buffer is fenced from MMA(c-1) by this loop's
        // single __syncthreads (per-warp program order + barrier), as in R5.
    }

    // ---- epilogue ----
    const float inv = 1.0f / 2049.0f;
#pragma unroll
    for (int mt = 0; mt < 2; mt++) {
        int row = m0 + wm * 32 + mt * 16 + g;
#pragma unroll
        for (int nt = 0; nt < 8; nt++) {
            int col = n0 + wn * 64 + nt * 8 + t * 2;
            if (col < K_) {
                float* p0 = out + (size_t)row * K_ + col;
                float* p1 = out + (size_t)(row + 8) * K_ + col;
                p0[0] = acc[mt][nt][0] * inv;
                p1[0] = acc[mt][nt][2] * inv;
                if (col + 1 < K_) {
                    p0[1] = acc[mt][nt][1] * inv;
                    p1[1] = acc[mt][nt][3] * inv;
                }
            }
        }
    }
}

// ================= launch =================
extern "C" void kernel_launch(void* const* d_in, const int* in_sizes, int n_in,
                              void* d_out, int out_size) {
    const float* x = (const float*)d_in[0];
    const float* w = (const float*)d_in[1];
    float* out = (float*)d_out;

    cudaFuncSetAttribute(gemm_kernel, cudaFuncAttributeMaxDynamicSharedMemorySize, GEMM_SMEM);

    tw_kernel<<<16, 256>>>();
    cas_kernel<<<(NCAS * M1 + 255) / 256, 256>>>();
    wpm_kernel<<<dim3(32, 2, 32), dim3(32, 32)>>>(w);
    fht_kernel<<<ROWS, 256>>>(x);
    mix_kernel<<<M1, 256>>>();
    gemm_kernel<<<dim3(NCAS / GBN, ROWS / GBM), 512, GEMM_SMEM>>>(out);
}

// round 9
// speedup vs baseline: 1.6327x; 1.5764x over previous
#include <cuda_runtime.h>
#include <cuda_fp16.h>
#include <cstdint>

#define B_   32
#define CI   64
#define CO   64
#define N_   4096
#define M1   1024      // modes1
#define K_   2049      // output length N/2+1
#define ROWS (B_*CI)   // 2048
#define NCAS 2304      // padded n rows for cas (9 * 256)

// -------- device scratch (static globals; no allocation) --------
__device__ float  g_tw[4096];                // butterfly twiddles: g_tw[h+j] = cas(2*pi*j/(2h))
__device__ __half g_casB[NCAS * M1];         // idht cas, fp16, chunk-major fragment layout (see below)
__device__ float  g_wp[M1 * 32 * CO];        // [k][i<32][o] = w[i,o,k] + w[63-i,o,k]
__device__ float  g_wm[M1 * 32 * CO];        // [k][i<32][o] = w[i,o,k] - w[63-i,o,k]
__device__ float  g_xhT[M1 * ROWS];          // FHT output, k-major: [k][b*CI+ci]
__device__ __half g_ohA[ROWS * M1];          // mixed modes (A matrix), fp16, fragment layout

// ---- fragment layouts (half index) ----
// A(m, k):  c=k>>5, s=(k>>4)&1, t=(k>>1)&3, mrow=(m>>4)*8+(m&7),
//           j = (k&1) + 2*((m>>3)&1) + 4*((k>>3)&1)
//           idx = (((c*2+s)*1024 + mrow)*4 + t)*8 + j
//   => one uint4 at [(c*2+s)*1024 + mrow][t] is a full mma A fragment
//      {x,y,z,w} = {(g,klo),(g+8,klo),(g,khi),(g+8,khi)} half2 pairs.
// B(n, k):  c=k>>5, t=(k>>1)&3, j = (k&1) + 2*((k>>3)&1) + 4*((k>>4)&1)
//           idx = ((c*NCAS + n)*4 + t)*8 + j
//   => one uint4 = B fragments for both k16 halves of chunk c:
//      {x,y} = s=0 {b0,b1}, {z,w} = s=1 {b0,b1}.

#define TWO_PI_F 6.283185307179586f

// ================= setup kernels =================
__global__ void tw_kernel() {
    int t = blockIdx.x * blockDim.x + threadIdx.x;
    if (t < 1 || t >= 4096) return;
    int h = 1 << (31 - __clz(t));
    int j = t - h;
    float ang = (TWO_PI_F * (float)j) / (float)(2 * h);
    float s, c; sincosf(ang, &s, &c);
    g_tw[t] = c + s;
}

// cas values in B fragment layout; angle follows the reference's f32 op order,
// then exact mod-2pi reduction (13b+24b split) to keep sincosf on the fast path.
__global__ void cas_kernel() {
    long idx = (long)blockIdx.x * blockDim.x + threadIdx.x;
    if (idx >= (long)NCAS * M1) return;
    int j = (int)(idx & 7);
    int t = (int)((idx >> 3) & 3);
    long rest = idx >> 5;
    int n = (int)(rest % NCAS);
    int c = (int)(rest / NCAS);
    int k = c * 32 + ((j >> 2) & 1) * 16 + ((j >> 1) & 1) * 8 + t * 2 + (j & 1);
    float ang = (TWO_PI_F * ((float)k * (float)n)) / 2049.0f;   // <= ~7224
    float q = rintf(ang * 0.15915494309189535f);
    float r = fmaf(-q, 6.2822265625f, ang);                     // exact (13b*11b)
    r = fmaf(-q, 9.5874467958647648e-4f, r);                    // |r| <= pi + eps
    float s, c2; sincosf(r, &s, &c2);
    g_casB[idx] = __float2half(c2 + s);
}

// fold + transpose weights, halved via i<->63-i symmetry
__global__ void wpm_kernel(const float* __restrict__ w) {
    __shared__ float sp[32][33];
    __shared__ float sm[32][33];
    int i  = blockIdx.z;                // 0..31
    int o0 = blockIdx.y * 32;
    int k0 = blockIdx.x * 32;
    int tx = threadIdx.x, ty = threadIdx.y;
    size_t off1 = ((size_t)i        * CO + (o0 + ty)) * M1 + k0 + tx;
    size_t off2 = ((size_t)(63 - i) * CO + (o0 + ty)) * M1 + k0 + tx;
    float a = w[off1], b = w[off2];
    sp[ty][tx] = a + b;
    sm[ty][tx] = a - b;
    __syncthreads();
    size_t woff = (size_t)(k0 + ty) * (32 * CO) + (size_t)i * CO + (o0 + tx);
    g_wp[woff] = sp[tx][ty];
    g_wm[woff] = sm[tx][ty];
}

// ================= FHT: 3-phase register-resident radix-16 =================
__global__ void __launch_bounds__(256) fht_kernel(const float* __restrict__ x) {
    __shared__ float s[N_ + N_ / 16];
    const int tid = threadIdx.x;
    const int row = blockIdx.x;
    const float* xr = x + (size_t)row * N_;

#pragma unroll
    for (int it = 0; it < 4; it++) {
        int n = tid * 4 + it * 1024;
        float4 v = *(const float4*)(xr + n);
        int p = n + (n >> 4);
        s[p] = v.x; s[p + 1] = v.y; s[p + 2] = v.z; s[p + 3] = v.w;
    }
    __syncthreads();

    float r[16];
    const int bt = __brev((unsigned)tid) >> 24;
#pragma unroll
    for (int q = 0; q < 16; q++) {
        int br = __brev((unsigned)q) >> 28;
        int idx = br * 256 + bt;
        r[q] = s[idx + (idx >> 4)];
    }
#pragma unroll
    for (int hs = 1; hs <= 8; hs <<= 1) {
#pragma unroll
        for (int q = 0; q < 16; q++) {
            if ((q & hs) == 0) {
                float tw = g_tw[hs + (q & (hs - 1))];
                float u = r[q], v = r[q + hs];
                float tv = tw * v;
                r[q] = u + tv; r[q + hs] = u - tv;
            }
        }
    }
    __syncthreads();
#pragma unroll
    for (int q = 0; q < 16; q++) {
        int idx = 16 * tid + q;
        s[idx + (idx >> 4)] = r[q];
    }
    __syncthreads();

    const int hi = tid >> 4, lo = tid & 15;
#pragma unroll
    for (int q = 0; q < 16; q++) {
        int idx = hi * 256 + q * 16 + lo;
        r[q] = s[idx + (idx >> 4)];
    }
#pragma unroll
    for (int hb = 1; hb <= 8; hb <<= 1) {
        int h = hb * 16;
#pragma unroll
        for (int q = 0; q < 16; q++) {
            if ((q & hb) == 0) {
                float tw = g_tw[h + (q & (hb - 1)) * 16 + lo];
                float u = r[q], v = r[q + hb];
                float tv = tw * v;
                r[q] = u + tv; r[q + hb] = u - tv;
            }
        }
    }
    __syncthreads();
#pragma unroll
    for (int q = 0; q < 16; q++) {
        int idx = hi * 256 + q * 16 + lo;
        s[idx + (idx >> 4)] = r[q];
    }
    __syncthreads();

#pragma unroll
    for (int q = 0; q < 16; q++) {
        int idx = q * 256 + tid;
        r[q] = s[idx + (idx >> 4)];
    }
#pragma unroll
    for (int hb = 1; hb <= 8; hb <<= 1) {
        int h = hb * 256;
#pragma unroll
        for (int q = 0; q < 16; q++) {
            if ((q & hb) == 0) {
                float tw = g_tw[h + (q & (hb - 1)) * 256 + tid];
                float u = r[q], v = r[q + hb];
                float tv = tw * v;
                r[q] = u + tv; r[q + hb] = u - tv;
            }
        }
    }
#pragma unroll
    for (int q = 0; q < 4; q++)
        g_xhT[(size_t)(q * 256 + tid) * ROWS + row] = r[q];
}

// ================= mode mixing -> fp16 fragment layout =================
__global__ void __launch_bounds__(256) mix_kernel() {
    int k = blockIdx.x;
    __shared__ float sYp[B_ * 32];      // [b][i<32] = X[b][i] + X[b][63-i]
    __shared__ float sYm[B_ * 32];      // [b][i<32] = X[b][i] - X[b][63-i]
    __shared__ float sWp[32 * CO];
    __shared__ float sWm[32 * CO];
    const float* Xk = g_xhT + (size_t)k * ROWS;
    const float* wp = g_wp  + (size_t)k * 32 * CO;
    const float* wm = g_wm  + (size_t)k * 32 * CO;
    for (int idx = threadIdx.x; idx < B_ * 32; idx += 256) {
        int b = idx >> 5, i = idx & 31;
        float u = Xk[b * 64 + i], v = Xk[b * 64 + 63 - i];
        sYp[idx] = u + v;
        sYm[idx] = u - v;
    }
    for (int idx = threadIdx.x; idx < 32 * CO; idx += 256) { sWp[idx] = wp[idx]; sWm[idx] = wm[idx]; }
    __syncthreads();
    int o  = threadIdx.x & 63;
    int bq = threadIdx.x >> 6;
    float acc[8];
#pragma unroll
    for (int rr = 0; rr < 8; rr++) acc[rr] = 0.f;
    for (int i = 0; i < 32; i++) {
        float wpv = sWp[i * CO + o];
        float wmv = sWm[i * CO + o];
#pragma unroll
        for (int rr = 0; rr < 8; rr++) {
            int b = bq * 8 + rr;
            acc[rr] += sYp[b * 32 + i] * wpv;
            acc[rr] += sYm[(31 - b) * 32 + i] * wmv;
        }
    }
    // write A = out_ht[m][k], m = b*64+o, in fp16 fragment layout
    const int c = k >> 5, s = (k >> 4) & 1, t = (k >> 1) & 3;
    const int jk = (k & 1) + 4 * ((k >> 3) & 1);
    const long base = (long)(c * 2 + s) * 1024;
#pragma unroll
    for (int rr = 0; rr < 8; rr++) {
        int m = (bq * 8 + rr) * 64 + o;
        int mrow = (m >> 4) * 8 + (m & 7);
        int j = jk + 2 * ((m >> 3) & 1);
        g_ohA[((base + mrow) * 4 + t) * 8 + j] = __float2half(0.5f * acc[rr]);
    }
}

// ================= idht GEMM: mma.sync fp16, smem-free =================
// out[m][n] = (1/2049) * sum_k A[m][k] * B[n][k]
// CTA tile 64m x 256n, 8 warps (2 wm x 4 wn), warp tile 32x64.
// Operands pre-permuted in global: each uint4 LDG is a ready fragment.
#define GNCH 32        // k chunks of 32

#define MMA16(d, a, b0, b1) \
    asm volatile("mma.sync.aligned.m16n8k16.row.col.f32.f16.f16.f32 " \
        "{%0,%1,%2,%3}, {%4,%5,%6,%7}, {%8,%9}, {%0,%1,%2,%3};" \
        : "+f"((d)[0]), "+f"((d)[1]), "+f"((d)[2]), "+f"((d)[3]) \
        : "r"((a).x), "r"((a).y), "r"((a).z), "r"((a).w), "r"(b0), "r"(b1))

__global__ void __launch_bounds__(256, 2) gemm_kernel(float* __restrict__ out) {
    const int tid  = threadIdx.x;
    const int wid  = tid >> 5;
    const int lane = tid & 31;
    const int g    = lane >> 2;        // fragment row group
    const int t    = lane & 3;         // fragment k-slot
    const int wm   = wid & 1;          // warp M strip (0..1)
    const int wn   = wid >> 1;         // warp N strip (0..3)
    const int m0   = blockIdx.y * 64;
    const int n0   = blockIdx.x * 256;

    const int m_base = m0 + wm * 32;
    const int n_base = n0 + wn * 64;
    const int mr8    = m_base >> 4;    // mrow block (x8)

    const uint4* Au = (const uint4*)g_ohA;   // [(c*2+s)*1024 + mrow][t]
    const uint4* Bu = (const uint4*)g_casB;  // [c*NCAS + n][t]

    float acc[2][8][4];
#pragma unroll
    for (int a = 0; a < 2; a++)
#pragma unroll
        for (int b = 0; b < 8; b++)
#pragma unroll
            for (int c = 0; c < 4; c++) acc[a][b][c] = 0.f;

#pragma unroll 2
    for (int c = 0; c < GNCH; c++) {
        uint4 af[2][2], bf[8];
#pragma unroll
        for (int s = 0; s < 2; s++)
#pragma unroll
            for (int mt = 0; mt < 2; mt++)
                af[mt][s] = __ldg(Au + ((long)(c * 2 + s) * 1024 + (mr8 + mt) * 8 + g) * 4 + t);
#pragma unroll
        for (int nt = 0; nt < 8; nt++)
            bf[nt] = __ldg(Bu + ((long)c * NCAS + n_base + nt * 8 + g) * 4 + t);
#pragma unroll
        for (int nt = 0; nt < 8; nt++) {
#pragma unroll
            for (int mt = 0; mt < 2; mt++) {
                MMA16(acc[mt][nt], af[mt][0], bf[nt].x, bf[nt].y);
                MMA16(acc[mt][nt], af[mt][1], bf[nt].z, bf[nt].w);
            }
        }
    }

    // ---- epilogue ----
    const float inv = 1.0f / 2049.0f;
#pragma unroll
    for (int mt = 0; mt < 2; mt++) {
        int row = m_base + mt * 16 + g;
#pragma unroll
        for (int nt = 0; nt < 8; nt++) {
            int col = n_base + nt * 8 + t * 2;
            if (col < K_) {
                float* p0 = out + (size_t)row * K_ + col;
                float* p1 = out + (size_t)(row + 8) * K_ + col;
                p0[0] = acc[mt][nt][0] * inv;
                p1[0] = acc[mt][nt][2] * inv;
                if (col + 1 < K_) {
                    p0[1] = acc[mt][nt][1] * inv;
                    p1[1] = acc[mt][nt][3] * inv;
                }
            }
        }
    }
}

// ================= launch =================
extern "C" void kernel_launch(void* const* d_in, const int* in_sizes, int n_in,
                              void* d_out, int out_size) {
    const float* x = (const float*)d_in[0];
    const float* w = (const float*)d_in[1];
    float* out = (float*)d_out;

    tw_kernel<<<16, 256>>>();
    cas_kernel<<<(NCAS * M1 + 255) / 256, 256>>>();
    wpm_kernel<<<dim3(32, 2, 32), dim3(32, 32)>>>(w);
    fht_kernel<<<ROWS, 256>>>(x);
    mix_kernel<<<M1, 256>>>();
    gemm_kernel<<<dim3(NCAS / 256, ROWS / 64), 256>>>(out);
}

// round 10
// speedup vs baseline: 1.7117x; 1.0484x over previous
#include <cuda_runtime.h>
#include <cuda_fp16.h>
#include <cstdint>

#define B_   32
#define CI   64
#define CO   64
#define N_   4096
#define M1   1024      // modes1
#define K_   2049      // output length N/2+1
#define ROWS (B_*CI)   // 2048
#define NCAS 2304      // padded n rows for cas (9 * 256)

// -------- device scratch (static globals; no allocation) --------
__device__ float  g_tw[4096];                // butterfly twiddles: g_tw[h+j] = cas(2*pi*j/(2h))
__device__ __half g_casB[NCAS * M1];         // idht cas, fp16, chunk-major fragment layout
__device__ float  g_wp[M1 * 32 * CO];        // [k][i<32][o] = w[i,o,k] + w[63-i,o,k]
__device__ float  g_wm[M1 * 32 * CO];        // [k][i<32][o] = w[i,o,k] - w[63-i,o,k]
__device__ float  g_xh [ROWS * M1];          // FHT output, row-major: [row][k]  (coalesced writes)
__device__ float  g_xhT[M1 * ROWS];          // FHT output transposed, k-major: [k][row]
__device__ __half g_ohP[M1 * ROWS];          // mixed modes, plain k-major: [k][m] (coalesced writes)
__device__ __half g_ohA[ROWS * M1];          // mixed modes (A matrix), fp16, mma fragment layout

// ---- fragment layouts (half index) ----
// A(m, k):  c=k>>5, s=(k>>4)&1, t=(k>>1)&3, mrow=(m>>4)*8+(m&7),
//           j = (k&1) + 2*((m>>3)&1) + 4*((k>>3)&1)
//           idx = (((c*2+s)*1024 + mrow)*4 + t)*8 + j
// B(n, k):  c=k>>5, t=(k>>1)&3, j = (k&1) + 2*((k>>3)&1) + 4*((k>>4)&1)
//           idx = ((c*NCAS + n)*4 + t)*8 + j

#define TWO_PI_F 6.283185307179586f

// ================= setup kernels =================
__global__ void tw_kernel() {
    int t = blockIdx.x * blockDim.x + threadIdx.x;
    if (t < 1 || t >= 4096) return;
    int h = 1 << (31 - __clz(t));
    int j = t - h;
    float ang = (TWO_PI_F * (float)j) / (float)(2 * h);
    float s, c; sincosf(ang, &s, &c);
    g_tw[t] = c + s;
}

// cas values in B fragment layout; angle follows the reference's f32 op order,
// then exact mod-2pi reduction (13b+24b split) to keep sincosf on the fast path.
__global__ void cas_kernel() {
    long idx = (long)blockIdx.x * blockDim.x + threadIdx.x;
    if (idx >= (long)NCAS * M1) return;
    int j = (int)(idx & 7);
    int t = (int)((idx >> 3) & 3);
    long rest = idx >> 5;
    int n = (int)(rest % NCAS);
    int c = (int)(rest / NCAS);
    int k = c * 32 + ((j >> 2) & 1) * 16 + ((j >> 1) & 1) * 8 + t * 2 + (j & 1);
    float ang = (TWO_PI_F * ((float)k * (float)n)) / 2049.0f;   // <= ~7224
    float q = rintf(ang * 0.15915494309189535f);
    float r = fmaf(-q, 6.2822265625f, ang);                     // exact (13b*11b)
    r = fmaf(-q, 9.5874467958647648e-4f, r);                    // |r| <= pi + eps
    float s, c2; sincosf(r, &s, &c2);
    g_casB[idx] = __float2half(c2 + s);
}

// fold + transpose weights, halved via i<->63-i symmetry
__global__ void wpm_kernel(const float* __restrict__ w) {
    __shared__ float sp[32][33];
    __shared__ float sm[32][33];
    int i  = blockIdx.z;                // 0..31
    int o0 = blockIdx.y * 32;
    int k0 = blockIdx.x * 32;
    int tx = threadIdx.x, ty = threadIdx.y;
    size_t off1 = ((size_t)i        * CO + (o0 + ty)) * M1 + k0 + tx;
    size_t off2 = ((size_t)(63 - i) * CO + (o0 + ty)) * M1 + k0 + tx;
    float a = w[off1], b = w[off2];
    sp[ty][tx] = a + b;
    sm[ty][tx] = a - b;
    __syncthreads();
    size_t woff = (size_t)(k0 + ty) * (32 * CO) + (size_t)i * CO + (o0 + tx);
    g_wp[woff] = sp[tx][ty];
    g_wm[woff] = sm[tx][ty];
}

// ================= FHT: 3-phase register-resident radix-16 =================
__global__ void __launch_bounds__(256) fht_kernel(const float* __restrict__ x) {
    __shared__ float s[N_ + N_ / 16];
    const int tid = threadIdx.x;
    const int row = blockIdx.x;
    const float* xr = x + (size_t)row * N_;

#pragma unroll
    for (int it = 0; it < 4; it++) {
        int n = tid * 4 + it * 1024;
        float4 v = *(const float4*)(xr + n);
        int p = n + (n >> 4);
        s[p] = v.x; s[p + 1] = v.y; s[p + 2] = v.z; s[p + 3] = v.w;
    }
    __syncthreads();

    float r[16];
    const int bt = __brev((unsigned)tid) >> 24;
#pragma unroll
    for (int q = 0; q < 16; q++) {
        int br = __brev((unsigned)q) >> 28;
        int idx = br * 256 + bt;
        r[q] = s[idx + (idx >> 4)];
    }
#pragma unroll
    for (int hs = 1; hs <= 8; hs <<= 1) {
#pragma unroll
        for (int q = 0; q < 16; q++) {
            if ((q & hs) == 0) {
                float tw = g_tw[hs + (q & (hs - 1))];
                float u = r[q], v = r[q + hs];
                float tv = tw * v;
                r[q] = u + tv; r[q + hs] = u - tv;
            }
        }
    }
    __syncthreads();
#pragma unroll
    for (int q = 0; q < 16; q++) {
        int idx = 16 * tid + q;
        s[idx + (idx >> 4)] = r[q];
    }
    __syncthreads();

    const int hi = tid >> 4, lo = tid & 15;
#pragma unroll
    for (int q = 0; q < 16; q++) {
        int idx = hi * 256 + q * 16 + lo;
        r[q] = s[idx + (idx >> 4)];
    }
#pragma unroll
    for (int hb = 1; hb <= 8; hb <<= 1) {
        int h = hb * 16;
#pragma unroll
        for (int q = 0; q < 16; q++) {
            if ((q & hb) == 0) {
                float tw = g_tw[h + (q & (hb - 1)) * 16 + lo];
                float u = r[q], v = r[q + hb];
                float tv = tw * v;
                r[q] = u + tv; r[q + hb] = u - tv;
            }
        }
    }
    __syncthreads();
#pragma unroll
    for (int q = 0; q < 16; q++) {
        int idx = hi * 256 + q * 16 + lo;
        s[idx + (idx >> 4)] = r[q];
    }
    __syncthreads();

#pragma unroll
    for (int q = 0; q < 16; q++) {
        int idx = q * 256 + tid;
        r[q] = s[idx + (idx >> 4)];
    }
#pragma unroll
    for (int hb = 1; hb <= 8; hb <<= 1) {
        int h = hb * 256;
#pragma unroll
        for (int q = 0; q < 16; q++) {
            if ((q & hb) == 0) {
                float tw = g_tw[h + (q & (hb - 1)) * 256 + tid];
                float u = r[q], v = r[q + hb];
                float tv = tw * v;
                r[q] = u + tv; r[q + hb] = u - tv;
            }
        }
    }
    // coalesced row-major write of first M1 modes
#pragma unroll
    for (int q = 0; q < 4; q++)
        g_xh[(size_t)row * M1 + q * 256 + tid] = r[q];
}

// ================= transpose: g_xh[2048][1024] -> g_xhT[1024][2048] =================
__global__ void __launch_bounds__(256) tr_kernel() {
    __shared__ float t[32][33];
    int c0 = blockIdx.x * 32;   // k
    int r0 = blockIdx.y * 32;   // row
    int tx = threadIdx.x, ty = threadIdx.y;
#pragma unroll
    for (int i = ty; i < 32; i += 8)
        t[i][tx] = g_xh[(size_t)(r0 + i) * M1 + c0 + tx];
    __syncthreads();
#pragma unroll
    for (int i = ty; i < 32; i += 8)
        g_xhT[(size_t)(c0 + i) * ROWS + r0 + tx] = t[tx][i];
}

// ================= mode mixing (symmetry-folded), plain coalesced output =================
__global__ void __launch_bounds__(256) mix_kernel() {
    int k = blockIdx.x;
    __shared__ float sYp[B_ * 32];      // [b][i<32] = X[b][i] + X[b][63-i]
    __shared__ float sYm[B_ * 32];      // [b][i<32] = X[b][i] - X[b][63-i]
    __shared__ float sWp[32 * CO];
    __shared__ float sWm[32 * CO];
    const float* Xk = g_xhT + (size_t)k * ROWS;
    const float* wp = g_wp  + (size_t)k * 32 * CO;
    const float* wm = g_wm  + (size_t)k * 32 * CO;
    for (int idx = threadIdx.x; idx < B_ * 32; idx += 256) {
        int b = idx >> 5, i = idx & 31;
        float u = Xk[b * 64 + i], v = Xk[b * 64 + 63 - i];
        sYp[idx] = u + v;
        sYm[idx] = u - v;
    }
    for (int idx = threadIdx.x; idx < 32 * CO; idx += 256) { sWp[idx] = wp[idx]; sWm[idx] = wm[idx]; }
    __syncthreads();
    int o  = threadIdx.x & 63;
    int bq = threadIdx.x >> 6;
    float acc[8];
#pragma unroll
    for (int rr = 0; rr < 8; rr++) acc[rr] = 0.f;
    for (int i = 0; i < 32; i++) {
        float wpv = sWp[i * CO + o];
        float wmv = sWm[i * CO + o];
#pragma unroll
        for (int rr = 0; rr < 8; rr++) {
            int b = bq * 8 + rr;
            acc[rr] += sYp[b * 32 + i] * wpv;
            acc[rr] += sYm[(31 - b) * 32 + i] * wmv;
        }
    }
    __half* ok = g_ohP + (size_t)k * ROWS;
#pragma unroll
    for (int rr = 0; rr < 8; rr++)
        ok[(bq * 8 + rr) * 64 + o] = __float2half(0.5f * acc[rr]);   // coalesced
}

// ================= repack A: plain k-major -> mma fragment layout =================
__global__ void __launch_bounds__(256) repackA_kernel() {
    __shared__ __half sT[32 * 256];     // [kk][m_local]
    const int c  = blockIdx.y;          // k-chunk 0..31
    const int m0 = blockIdx.x * 256;    // m tile
    const int tid = threadIdx.x;
    const uint4* inU = (const uint4*)g_ohP;
#pragma unroll
    for (int it = 0; it < 4; it++) {
        int kk = it * 8 + (tid >> 5);
        int u  = tid & 31;
        ((uint4*)sT)[kk * 32 + u] = inU[(long)(c * 32 + kk) * 256 + (m0 >> 3) + u];
    }
    __syncthreads();
    uint4* outU = (uint4*)g_ohA;
#pragma unroll
    for (int ii = 0; ii < 4; ii++) {
        int idx = ii * 256 + tid;                 // 0..1023
        int s   = idx >> 9;
        int rem = idx & 511;
        int mrl = rem >> 2;                       // mrow local 0..127
        int t   = rem & 3;
        uint32_t p[4];
#pragma unroll
        for (int jp = 0; jp < 4; jp++) {          // j = jp*2, jp*2+1
            int j0 = jp * 2;
            int kk0 = s * 16 + t * 2 + 8 * ((j0 >> 2) & 1);
            int ml0 = ((mrl >> 3) << 4) + 8 * ((j0 >> 1) & 1) + (mrl & 7);
            uint32_t lo = __half_as_ushort(sT[kk0 * 256 + ml0]);        // j even: k bit0=0
            uint32_t hi = __half_as_ushort(sT[(kk0 + 1) * 256 + ml0]);  // j odd:  k bit0=1
            p[jp] = lo | (hi << 16);
        }
        uint4 v; v.x = p[0]; v.y = p[1]; v.z = p[2]; v.w = p[3];
        outU[((long)(c * 2 + s) * 1024 + (m0 >> 1) + mrl) * 4 + t] = v;  // coalesced
    }
}

// ================= idht GEMM: mma.sync fp16, smem-free, one wave =================
// CTA tile 128m x 256n, 512 threads (16 warps, 4wm x 4wn), warp tile 32x64.
#define GNCH 32

#define MMA16(d, a, b0, b1) \
    asm volatile("mma.sync.aligned.m16n8k16.row.col.f32.f16.f16.f32 " \
        "{%0,%1,%2,%3}, {%4,%5,%6,%7}, {%8,%9}, {%0,%1,%2,%3};" \
        : "+f"((d)[0]), "+f"((d)[1]), "+f"((d)[2]), "+f"((d)[3]) \
        : "r"((a).x), "r"((a).y), "r"((a).z), "r"((a).w), "r"(b0), "r"(b1))

__global__ void __launch_bounds__(512, 1) gemm_kernel(float* __restrict__ out) {
    const int tid  = threadIdx.x;
    const int wid  = tid >> 5;
    const int lane = tid & 31;
    const int g    = lane >> 2;
    const int t    = lane & 3;
    const int wm   = wid & 3;          // 0..3, 32-row strip
    const int wn   = wid >> 2;         // 0..3, 64-col strip
    const int m0   = blockIdx.y * 128;
    const int n0   = blockIdx.x * 256;

    const int m_base = m0 + wm * 32;
    const int n_base = n0 + wn * 64;
    const int mr8    = m_base >> 4;

    const uint4* Au = (const uint4*)g_ohA;
    const uint4* Bu = (const uint4*)g_casB;

    float acc[2][8][4];
#pragma unroll
    for (int a = 0; a < 2; a++)
#pragma unroll
        for (int b = 0; b < 8; b++)
#pragma unroll
            for (int c = 0; c < 4; c++) acc[a][b][c] = 0.f;

#pragma unroll 2
    for (int c = 0; c < GNCH; c++) {
        uint4 af[2][2];
#pragma unroll
        for (int s = 0; s < 2; s++)
#pragma unroll
            for (int mt = 0; mt < 2; mt++)
                af[mt][s] = __ldg(Au + ((long)(c * 2 + s) * 1024 + (mr8 + mt) * 8 + g) * 4 + t);
#pragma unroll
        for (int nh = 0; nh < 2; nh++) {
            uint4 bf[4];
#pragma unroll
            for (int n4 = 0; n4 < 4; n4++)
                bf[n4] = __ldg(Bu + ((long)c * NCAS + n_base + (nh * 4 + n4) * 8 + g) * 4 + t);
#pragma unroll
            for (int n4 = 0; n4 < 4; n4++) {
#pragma unroll
                for (int mt = 0; mt < 2; mt++) {
                    MMA16(acc[mt][nh * 4 + n4], af[mt][0], bf[n4].x, bf[n4].y);
                    MMA16(acc[mt][nh * 4 + n4], af[mt][1], bf[n4].z, bf[n4].w);
                }
            }
        }
    }

    const float inv = 1.0f / 2049.0f;
#pragma unroll
    for (int mt = 0; mt < 2; mt++) {
        int row = m_base + mt * 16 + g;
#pragma unroll
        for (int nt = 0; nt < 8; nt++) {
            int col = n_base + nt * 8 + t * 2;
            if (col < K_) {
                float* p0 = out + (size_t)row * K_ + col;
                float* p1 = out + (size_t)(row + 8) * K_ + col;
                p0[0] = acc[mt][nt][0] * inv;
                p1[0] = acc[mt][nt][2] * inv;
                if (col + 1 < K_) {
                    p0[1] = acc[mt][nt][1] * inv;
                    p1[1] = acc[mt][nt][3] * inv;
                }
            }
        }
    }
}

// ================= launch =================
extern "C" void kernel_launch(void* const* d_in, const int* in_sizes, int n_in,
                              void* d_out, int out_size) {
    const float* x = (const float*)d_in[0];
    const float* w = (const float*)d_in[1];
    float* out = (float*)d_out;

    tw_kernel<<<16, 256>>>();
    cas_kernel<<<(NCAS * M1 + 255) / 256, 256>>>();
    wpm_kernel<<<dim3(32, 2, 32), dim3(32, 32)>>>(w);
    fht_kernel<<<ROWS, 256>>>(x);
    tr_kernel<<<dim3(M1 / 32, ROWS / 32), dim3(32, 8)>>>();
    mix_kernel<<<M1, 256>>>();
    repackA_kernel<<<dim3(ROWS / 256, 32), 256>>>();
    gemm_kernel<<<dim3(NCAS / 256, ROWS / 128), 512>>>(out);
}